// round 9
// baseline (speedup 1.0000x reference)
#include <cuda_runtime.h>
#include <float.h>

#define H_IN   161
#define W_IN   161
#define C      128
#define H_OUT  641
#define W_OUT  641
#define NPIX   (H_OUT * W_OUT)
#define NEGV   (-1000000000.0f)
#define LOG2E  1.4426950408889634f

#define NCOLS   65
#define STRIDE  130       // even (8B align for LDS.64), mod 32 == 2

typedef unsigned long long ull;

// Per-slot classification results (phase A -> phase B)
__device__ int      g_maskid[128];
__device__ int      g_sem[128];
__device__ unsigned g_detmask[4];
__device__ int      g_hasdet;
__device__ int      g_alldet;

// ---------------------------------------------------------------------------
// Phase A: 512 threads, 4-way split scan per slot + ballot cumsum.
// ---------------------------------------------------------------------------
__global__ void classify_kernel(const float* __restrict__ probs /*128x134*/) {
    __shared__ unsigned char sdet[128];
    __shared__ unsigned wmask[4];

    const int t    = threadIdx.x;          // 0..511
    const int lane = t & 31;
    const int s    = t >> 2;               // slot 0..127
    const int part = t & 3;

    const int c0 = part * 34;
    const int c1 = (c0 + 34 < 133) ? (c0 + 34) : 133;
    const float* row = probs + s * 134;
    float best = -FLT_MAX;
    int bi = c0;
    for (int c = c0; c < c1; ++c) {
        float v = row[c];
        if (v > best) { best = v; bi = c; }    // strict >: first occurrence
    }
    const unsigned pm = 0xFu << (lane & 28);
    #pragma unroll
    for (int off = 1; off <= 2; off <<= 1) {
        float ob  = __shfl_xor_sync(pm, best, off);
        int   obi = __shfl_xor_sync(pm, bi,   off);
        if (ob > best || (ob == best && obi < bi)) { best = ob; bi = obi; }
    }
    if (part == 0) {
        g_sem[s] = bi;
        sdet[s]  = (best >= 0.7f) ? 1 : 0;
    }
    __syncthreads();

    unsigned b = 0;
    if (t < 128) {
        b = __ballot_sync(0xffffffffu, sdet[t] != 0);
        if (lane == 0) wmask[t >> 5] = b;
    }
    __syncthreads();

    if (t < 128) {
        int cnt = __popc(b & (0xffffffffu >> (31 - lane)));
        for (int k = 0; k < (t >> 5); ++k) cnt += __popc(wmask[k]);
        g_maskid[t] = cnt - 1;
        if (t == 0) {
            int tot = __popc(wmask[0]) + __popc(wmask[1]) +
                      __popc(wmask[2]) + __popc(wmask[3]);
            g_detmask[0] = wmask[0]; g_detmask[1] = wmask[1];
            g_detmask[2] = wmask[2]; g_detmask[3] = wmask[3];
            g_hasdet = (tot > 0)   ? 1 : 0;
            g_alldet = (tot == 128)? 1 : 0;
        }
    }
}

// ---------------------------------------------------------------------------
// Packed f32x2 helpers
// ---------------------------------------------------------------------------
__device__ __forceinline__ ull f2x2_mul(ull a, ull b) {
    ull r; asm("mul.rn.f32x2 %0, %1, %2;" : "=l"(r) : "l"(a), "l"(b)); return r;
}
__device__ __forceinline__ ull f2x2_fma(ull a, ull b, ull c) {
    ull r; asm("fma.rn.f32x2 %0, %1, %2, %3;" : "=l"(r) : "l"(a), "l"(b), "l"(c)); return r;
}
__device__ __forceinline__ ull f2x2_add(ull a, ull b) {
    ull r; asm("add.rn.f32x2 %0, %1, %2;" : "=l"(r) : "l"(a), "l"(b)); return r;
}
__device__ __forceinline__ ull f2x2_pack(float lo, float hi) {
    ull r; asm("mov.b64 %0, {%1, %2};" : "=l"(r) : "f"(lo), "f"(hi)); return r;
}
__device__ __forceinline__ void f2x2_unpack(ull v, float& lo, float& hi) {
    asm("mov.b64 {%0, %1}, %2;" : "=f"(lo), "=f"(hi) : "l"(v));
}
#define EX2(dst, src) asm("ex2.approx.f32 %0, %1;" : "=f"(dst) : "f"(src))

// Epilogue: find within-group channel of the per-pixel max (bit-identical
// recomputation of the main-loop v values; first occurrence on ties).
__device__ __forceinline__ int scan_group(const ull* pa, const ull* pb,
                                          ull QP, ull QN,
                                          int bg, float bv, int p) {
    ull a01 = pa[2 * bg], a23 = pa[2 * bg + 1];
    ull b01 = pb[2 * bg], b23 = pb[2 * bg + 1];
    ull q01 = f2x2_fma(b01, QP, f2x2_mul(a01, QN));
    ull q23 = f2x2_fma(b23, QP, f2x2_mul(a23, QN));
    ull u01 = a01, u23 = a23;
    for (int k = 0; k < p; ++k) {
        u01 = f2x2_add(u01, q01);
        u23 = f2x2_add(u23, q23);
    }
    float t0, t1, t2, t3;
    f2x2_unpack(u01, t0, t1);
    f2x2_unpack(u23, t2, t3);
    int r = 3;
    if (t2 == bv) r = 2;
    if (t1 == bv) r = 1;
    if (t0 == bv) r = 0;
    return 4 * bg + r;
}

// ---------------------------------------------------------------------------
// Phase B: grid (3, 641). Block = one 64-quad segment of one row, 256 thr.
// Fast path: thread = (quad, channel-quarter). Per channel: one EX2(a), one
// EX2(q), geometric chain for the 4 sub-pixel exps; maxes in v-domain via
// packed adds. Quad shfl combine. General path = proven per-pixel loop.
// ---------------------------------------------------------------------------
__global__ void __launch_bounds__(256, 4)
postproc_kernel(const float* __restrict__ in, float* __restrict__ out) {
    __shared__ float sbuf[NCOLS * STRIDE];   // 33800 B
    __shared__ float sbias[128];
    __shared__ int   ssem[128];
    __shared__ int   smaskid[128];

    const int y  = blockIdx.y;
    const int y0 = y >> 2;
    const int y1 = min(y0 + 1, H_IN - 1);
    const float wy = (float)(y & 3) * 0.25f;
    const float w1 = wy * LOG2E;
    const float w0 = (1.0f - wy) * LOG2E;

    const int cb = blockIdx.x * 64;
    const int nc = min(NCOLS, W_IN - cb);

    // ---- fill: y-lerp (log2e-prescaled) into SMEM, stride 130 ----
    {
        const float4* r0 = (const float4*)(in + ((size_t)y0 * W_IN + cb) * C);
        const float4* r1 = (const float4*)(in + ((size_t)y1 * W_IN + cb) * C);
        const int nv = nc * 32;
        if ((y & 3) == 0) {
            #pragma unroll 4
            for (int i = threadIdx.x; i < nv; i += 256) {
                float4 a = r0[i];
                float* dst = sbuf + (i >> 5) * STRIDE + (i & 31) * 4;
                *(float2*)(dst)     = make_float2(a.x * w0, a.y * w0);
                *(float2*)(dst + 2) = make_float2(a.z * w0, a.w * w0);
            }
        } else {
            #pragma unroll 4
            for (int i = threadIdx.x; i < nv; i += 256) {
                float4 a = r0[i], b = r1[i];
                float* dst = sbuf + (i >> 5) * STRIDE + (i & 31) * 4;
                *(float2*)(dst)     = make_float2(a.x * w0 + b.x * w1, a.y * w0 + b.y * w1);
                *(float2*)(dst + 2) = make_float2(a.z * w0 + b.z * w1, a.w * w0 + b.w * w1);
            }
        }
        if (threadIdx.x < 128) {
            unsigned m = g_detmask[threadIdx.x >> 5];
            sbias[threadIdx.x] = ((m >> (threadIdx.x & 31)) & 1u) ? 0.0f : NEGV;
            ssem[threadIdx.x]    = g_sem[threadIdx.x];
            smaskid[threadIdx.x] = g_maskid[threadIdx.x];
        }
    }
    __syncthreads();

    const int lane = threadIdx.x & 31;

    if (g_alldet) {
        // ================= FAST PATH =================
        const int qd      = cb + (threadIdx.x >> 2);   // input column / quad id
        const int quarter = threadIdx.x & 3;           // channel quarter
        const bool active = (qd < W_IN);
        const unsigned pm = 0xFu << (lane & 28);

        float s0 = 0.f, s1 = 0.f, s2 = 0.f, s3 = 0.f;
        float bv0 = -FLT_MAX, bv1 = -FLT_MAX, bv2 = -FLT_MAX, bv3 = -FLT_MAX;
        int   bg0 = 0, bg1 = 0, bg2 = 0, bg3 = 0;
        int   bi0 = 0, bi1 = 0, bi2 = 0, bi3 = 0;

        if (active) {
            const int xx1 = min(qd + 1, W_IN - 1);
            const ull* pa = (const ull*)(sbuf + (qd  - cb) * STRIDE + quarter * 32);
            const ull* pb = (const ull*)(sbuf + (xx1 - cb) * STRIDE + quarter * 32);
            const ull QP = f2x2_pack(0.25f, 0.25f);
            const ull QN = f2x2_pack(-0.25f, -0.25f);

            #pragma unroll
            for (int g = 0; g < 8; ++g) {
                ull a01 = pa[2 * g], a23 = pa[2 * g + 1];
                ull b01 = pb[2 * g], b23 = pb[2 * g + 1];
                ull q01 = f2x2_fma(b01, QP, f2x2_mul(a01, QN));
                ull q23 = f2x2_fma(b23, QP, f2x2_mul(a23, QN));
                ull u101 = f2x2_add(a01,  q01), u123 = f2x2_add(a23,  q23);
                ull u201 = f2x2_add(u101, q01), u223 = f2x2_add(u123, q23);
                ull u301 = f2x2_add(u201, q01), u323 = f2x2_add(u223, q23);

                float fa0, fa1, fa2, fa3, fq0, fq1, fq2, fq3;
                f2x2_unpack(a01, fa0, fa1); f2x2_unpack(a23, fa2, fa3);
                f2x2_unpack(q01, fq0, fq1); f2x2_unpack(q23, fq2, fq3);
                float p10, p11, p12, p13, p20, p21, p22, p23, p30, p31, p32, p33;
                f2x2_unpack(u101, p10, p11); f2x2_unpack(u123, p12, p13);
                f2x2_unpack(u201, p20, p21); f2x2_unpack(u223, p22, p23);
                f2x2_unpack(u301, p30, p31); f2x2_unpack(u323, p32, p33);

                // per-pixel group maxes in v-domain
                float gm0 = fmaxf(fmaxf(fa0, fa1), fmaxf(fa2, fa3));
                float gm1 = fmaxf(fmaxf(p10, p11), fmaxf(p12, p13));
                float gm2 = fmaxf(fmaxf(p20, p21), fmaxf(p22, p23));
                float gm3 = fmaxf(fmaxf(p30, p31), fmaxf(p32, p33));
                if (gm0 > bv0) { bv0 = gm0; bg0 = g; }
                if (gm1 > bv1) { bv1 = gm1; bg1 = g; }
                if (gm2 > bv2) { bv2 = gm2; bg2 = g; }
                if (gm3 > bv3) { bv3 = gm3; bg3 = g; }

                // geometric exp chain: 2 EX2 per channel for all 4 pixels
                float e0, e1, e2, e3, r0, r1, r2, r3;
                EX2(e0, fa0); EX2(e1, fa1); EX2(e2, fa2); EX2(e3, fa3);
                EX2(r0, fq0); EX2(r1, fq1); EX2(r2, fq2); EX2(r3, fq3);
                s0 += e0; s0 += e1; s0 += e2; s0 += e3;
                s1 = fmaf(e0, r0, s1); s1 = fmaf(e1, r1, s1);
                s1 = fmaf(e2, r2, s1); s1 = fmaf(e3, r3, s1);
                float r20 = r0 * r0, r21 = r1 * r1, r22 = r2 * r2, r23 = r3 * r3;
                s2 = fmaf(e0, r20, s2); s2 = fmaf(e1, r21, s2);
                s2 = fmaf(e2, r22, s2); s2 = fmaf(e3, r23, s2);
                float r30 = r20 * r0, r31 = r21 * r1, r32 = r22 * r2, r33 = r23 * r3;
                s3 = fmaf(e0, r30, s3); s3 = fmaf(e1, r31, s3);
                s3 = fmaf(e2, r32, s3); s3 = fmaf(e3, r33, s3);
            }

            const int ch0 = quarter * 32;
            bi0 = ch0 + scan_group(pa, pb, QP, QN, bg0, bv0, 0);
            bi1 = ch0 + scan_group(pa, pb, QP, QN, bg1, bv1, 1);
            bi2 = ch0 + scan_group(pa, pb, QP, QN, bg2, bv2, 2);
            bi3 = ch0 + scan_group(pa, pb, QP, QN, bg3, bv3, 3);

            // combine across the 4 channel-quarters (quad shfl)
            #pragma unroll
            for (int off = 1; off <= 2; off <<= 1) {
                s0 += __shfl_xor_sync(pm, s0, off);
                s1 += __shfl_xor_sync(pm, s1, off);
                s2 += __shfl_xor_sync(pm, s2, off);
                s3 += __shfl_xor_sync(pm, s3, off);
                float ob; int oi;
                ob = __shfl_xor_sync(pm, bv0, off); oi = __shfl_xor_sync(pm, bi0, off);
                if (ob > bv0 || (ob == bv0 && oi < bi0)) { bv0 = ob; bi0 = oi; }
                ob = __shfl_xor_sync(pm, bv1, off); oi = __shfl_xor_sync(pm, bi1, off);
                if (ob > bv1 || (ob == bv1 && oi < bi1)) { bv1 = ob; bi1 = oi; }
                ob = __shfl_xor_sync(pm, bv2, off); oi = __shfl_xor_sync(pm, bi2, off);
                if (ob > bv2 || (ob == bv2 && oi < bi2)) { bv2 = ob; bi2 = oi; }
                ob = __shfl_xor_sync(pm, bv3, off); oi = __shfl_xor_sync(pm, bi3, off);
                if (ob > bv3 || (ob == bv3 && oi < bi3)) { bv3 = ob; bi3 = oi; }
            }

            if (quarter == 0) {
                float sv[4] = { s0, s1, s2, s3 };
                float bvv[4] = { bv0, bv1, bv2, bv3 };
                int   biv[4] = { bi0, bi1, bi2, bi3 };
                #pragma unroll
                for (int p4 = 0; p4 < 4; ++p4) {
                    const int px = 4 * qd + p4;
                    if (px < W_OUT) {
                        // pixel_conf > 0.4  <=>  s < 2.5 * 2^bv ; detected_pixel==1
                        float eb; EX2(eb, bvv[p4]);
                        const float cf = (sv[p4] < 2.5f * eb) ? 1.0f : 0.0f;
                        const int bi = biv[p4];
                        const int semI = ssem[bi];
                        const int p = y * W_OUT + px;
                        out[p]            = (float)(smaskid[bi] + 1);
                        out[NPIX + p]     = (float)semI;
                        out[2 * NPIX + p] = (semI < 80)  ? cf : 0.0f;
                        out[3 * NPIX + p] = (semI >= 80) ? cf : 0.0f;
                    }
                }
            }
        }
    } else {
        // ================= GENERAL PATH (rare) =================
        const int px = cb * 4 + threadIdx.x;
        if (px < W_OUT) {
            const int x0 = px >> 2;
            const int x1 = min(x0 + 1, W_IN - 1);
            const float wx   = (float)(px & 3) * 0.25f;
            const float omwx = 1.0f - wx;
            const ull* pa = (const ull*)(sbuf + (x0 - cb) * STRIDE);
            const ull* pb = (const ull*)(sbuf + (x1 - cb) * STRIDE);
            const ull* pg = (const ull*)sbias;

            float fm = -FLT_MAX, bv = -FLT_MAX, s = 0.0f;
            int bi = 0;
            #pragma unroll 8
            for (int c2 = 0; c2 < 64; ++c2) {
                float a0, a1, b0, b1, gg0, gg1;
                f2x2_unpack(pa[c2], a0, a1);
                f2x2_unpack(pb[c2], b0, b1);
                f2x2_unpack(pg[c2], gg0, gg1);
                {
                    float v = a0 * omwx + b0 * wx;
                    fm = fmaxf(fm, v);
                    float mv = v + gg0;
                    if (mv > bv) { bv = mv; bi = 2 * c2; }
                    float e; EX2(e, mv); s += e;
                }
                {
                    float v = a1 * omwx + b1 * wx;
                    fm = fmaxf(fm, v);
                    float mv = v + gg1;
                    if (mv > bv) { bv = mv; bi = 2 * c2 + 1; }
                    float e; EX2(e, mv); s += e;
                }
            }
            float eb; EX2(eb, bv);
            const float cf = (s < 2.5f * eb && fm == bv) ? 1.0f : 0.0f;

            float maskid, sem, thing, stuff;
            if (g_hasdet) {
                const int semI = ssem[bi];
                maskid = (float)(smaskid[bi] + 1);
                sem    = (float)semI;
                thing  = (semI < 80)  ? cf : 0.0f;
                stuff  = (semI >= 80) ? cf : 0.0f;
            } else {
                maskid = 1.0f; sem = 0.0f; thing = 0.0f; stuff = 0.0f;
            }
            const int p = y * W_OUT + px;
            out[p]            = maskid;
            out[NPIX + p]     = sem;
            out[2 * NPIX + p] = thing;
            out[3 * NPIX + p] = stuff;
        }
    }
}

// ---------------------------------------------------------------------------
extern "C" void kernel_launch(void* const* d_in, const int* in_sizes, int n_in,
                              void* d_out, int out_size) {
    const float* logits = (const float*)d_in[0];  // (161,161,128)
    const float* probs  = (const float*)d_in[1];  // (128,134)
    if (n_in >= 2 && in_sizes[0] < in_sizes[1]) { // safety: order by size
        const float* t = logits; logits = probs; probs = t;
    }
    float* out = (float*)d_out;

    classify_kernel<<<1, 512>>>(probs);
    postproc_kernel<<<dim3(3, H_OUT), 256>>>(logits, out);
}

// round 10
// speedup vs baseline: 1.1819x; 1.1819x over previous
#include <cuda_runtime.h>
#include <float.h>

#define H_IN   161
#define W_IN   161
#define C      128
#define H_OUT  641
#define W_OUT  641
#define NPIX   (H_OUT * W_OUT)
#define NEGV   (-1000000000.0f)
#define LOG2E  1.4426950408889634f

#define NCOLS    65
#define CSTRIDE  136      // column stride in floats: 136 mod 32 == 8
#define QSTRIDE  34       // quarter stride in floats: 34 mod 32 == 2

typedef unsigned long long ull;

// Per-slot classification results (phase A -> phase B)
__device__ int      g_maskid[128];
__device__ int      g_sem[128];
__device__ unsigned g_detmask[4];
__device__ int      g_hasdet;
__device__ int      g_alldet;

// ---------------------------------------------------------------------------
// Phase A: 1024 threads, 8-way split scan per slot + ballot cumsum.
// ---------------------------------------------------------------------------
__global__ void classify_kernel(const float* __restrict__ probs /*128x134*/) {
    __shared__ unsigned char sdet[128];
    __shared__ unsigned wmask[4];

    const int t    = threadIdx.x;          // 0..1023
    const int lane = t & 31;
    const int s    = t >> 3;               // slot 0..127
    const int part = t & 7;

    const int c0 = part * 17;
    const int c1 = (c0 + 17 < 133) ? (c0 + 17) : 133;
    const float* row = probs + s * 134;
    float best = -FLT_MAX;
    int bi = c0;
    for (int c = c0; c < c1; ++c) {
        float v = row[c];
        if (v > best) { best = v; bi = c; }    // strict >: first occurrence
    }
    const unsigned pm = 0xFFu << (lane & 24);
    #pragma unroll
    for (int off = 1; off <= 4; off <<= 1) {
        float ob  = __shfl_xor_sync(pm, best, off);
        int   obi = __shfl_xor_sync(pm, bi,   off);
        if (ob > best || (ob == best && obi < bi)) { best = ob; bi = obi; }
    }
    if (part == 0) {
        g_sem[s] = bi;
        sdet[s]  = (best >= 0.7f) ? 1 : 0;
    }
    __syncthreads();

    unsigned b = 0;
    if (t < 128) {
        b = __ballot_sync(0xffffffffu, sdet[t] != 0);
        if (lane == 0) wmask[t >> 5] = b;
    }
    __syncthreads();

    if (t < 128) {
        int cnt = __popc(b & (0xffffffffu >> (31 - lane)));
        for (int k = 0; k < (t >> 5); ++k) cnt += __popc(wmask[k]);
        g_maskid[t] = cnt - 1;
        if (t == 0) {
            int tot = __popc(wmask[0]) + __popc(wmask[1]) +
                      __popc(wmask[2]) + __popc(wmask[3]);
            g_detmask[0] = wmask[0]; g_detmask[1] = wmask[1];
            g_detmask[2] = wmask[2]; g_detmask[3] = wmask[3];
            g_hasdet = (tot > 0)   ? 1 : 0;
            g_alldet = (tot == 128)? 1 : 0;
        }
    }
}

// ---------------------------------------------------------------------------
// Packed f32x2 helpers
// ---------------------------------------------------------------------------
__device__ __forceinline__ ull f2x2_mul(ull a, ull b) {
    ull r; asm("mul.rn.f32x2 %0, %1, %2;" : "=l"(r) : "l"(a), "l"(b)); return r;
}
__device__ __forceinline__ ull f2x2_fma(ull a, ull b, ull c) {
    ull r; asm("fma.rn.f32x2 %0, %1, %2, %3;" : "=l"(r) : "l"(a), "l"(b), "l"(c)); return r;
}
__device__ __forceinline__ ull f2x2_add(ull a, ull b) {
    ull r; asm("add.rn.f32x2 %0, %1, %2;" : "=l"(r) : "l"(a), "l"(b)); return r;
}
__device__ __forceinline__ ull f2x2_pack(float lo, float hi) {
    ull r; asm("mov.b64 %0, {%1, %2};" : "=l"(r) : "f"(lo), "f"(hi)); return r;
}
__device__ __forceinline__ void f2x2_unpack(ull v, float& lo, float& hi) {
    asm("mov.b64 {%0, %1}, %2;" : "=f"(lo), "=f"(hi) : "l"(v));
}
#define EX2(dst, src) asm("ex2.approx.f32 %0, %1;" : "=f"(dst) : "f"(src))

// Epilogue: find within-group channel of the per-pixel max (bit-identical
// recomputation of the main-loop v values; first occurrence on ties).
__device__ __forceinline__ int scan_group(const ull* pa, const ull* pb,
                                          ull QP, ull QN,
                                          int bg, float bv, int p) {
    ull a01 = pa[2 * bg], a23 = pa[2 * bg + 1];
    ull b01 = pb[2 * bg], b23 = pb[2 * bg + 1];
    ull q01 = f2x2_fma(b01, QP, f2x2_mul(a01, QN));
    ull q23 = f2x2_fma(b23, QP, f2x2_mul(a23, QN));
    ull u01 = a01, u23 = a23;
    for (int k = 0; k < p; ++k) {
        u01 = f2x2_add(u01, q01);
        u23 = f2x2_add(u23, q23);
    }
    float t0, t1, t2, t3;
    f2x2_unpack(u01, t0, t1);
    f2x2_unpack(u23, t2, t3);
    int r = 3;
    if (t2 == bv) r = 2;
    if (t1 == bv) r = 1;
    if (t0 == bv) r = 0;
    return 4 * bg + r;
}

// ---------------------------------------------------------------------------
// Phase B: grid (3, 641). Block = one 64-quad segment of one row, 256 thr.
// SMEM layout: column-major, per-column 4 quarter-groups of 32 channels with
// 2-float pads (CSTRIDE=136, QSTRIDE=34) -> conflict-free LDS.64 in the quad
// scheme (lane residue = 8*quad + 2*quarter, all distinct per half-warp).
// Fast path: thread = (quad, channel-quarter). Per channel: EX2(a) + EX2(q)
// + geometric chain gives all 4 sub-pixel exps; maxes in v-domain.
// ---------------------------------------------------------------------------
__global__ void __launch_bounds__(256, 4)
postproc_kernel(const float* __restrict__ in, float* __restrict__ out) {
    __shared__ float sbuf[NCOLS * CSTRIDE];   // 35360 B
    __shared__ float sbias[128];
    __shared__ int   ssem[128];
    __shared__ int   smaskid[128];

    const int y  = blockIdx.y;
    const int y0 = y >> 2;
    const int y1 = min(y0 + 1, H_IN - 1);
    const float wy = (float)(y & 3) * 0.25f;
    const float w1 = wy * LOG2E;
    const float w0 = (1.0f - wy) * LOG2E;

    const int cb = blockIdx.x * 64;
    const int nc = min(NCOLS, W_IN - cb);

    // ---- fill: y-lerp (log2e-prescaled) into padded SMEM ----
    {
        const float4* r0 = (const float4*)(in + ((size_t)y0 * W_IN + cb) * C);
        const float4* r1 = (const float4*)(in + ((size_t)y1 * W_IN + cb) * C);
        const int nv = nc * 32;   // float4 count
        if ((y & 3) == 0) {
            #pragma unroll 4
            for (int i = threadIdx.x; i < nv; i += 256) {
                float4 a = r0[i];
                float* dst = sbuf + (i >> 5) * CSTRIDE
                                  + ((i & 31) >> 3) * QSTRIDE + (i & 7) * 4;
                *(float2*)(dst)     = make_float2(a.x * w0, a.y * w0);
                *(float2*)(dst + 2) = make_float2(a.z * w0, a.w * w0);
            }
        } else {
            #pragma unroll 4
            for (int i = threadIdx.x; i < nv; i += 256) {
                float4 a = r0[i], b = r1[i];
                float* dst = sbuf + (i >> 5) * CSTRIDE
                                  + ((i & 31) >> 3) * QSTRIDE + (i & 7) * 4;
                *(float2*)(dst)     = make_float2(a.x * w0 + b.x * w1, a.y * w0 + b.y * w1);
                *(float2*)(dst + 2) = make_float2(a.z * w0 + b.z * w1, a.w * w0 + b.w * w1);
            }
        }
        if (threadIdx.x < 128) {
            unsigned m = g_detmask[threadIdx.x >> 5];
            sbias[threadIdx.x] = ((m >> (threadIdx.x & 31)) & 1u) ? 0.0f : NEGV;
            ssem[threadIdx.x]    = g_sem[threadIdx.x];
            smaskid[threadIdx.x] = g_maskid[threadIdx.x];
        }
    }
    __syncthreads();

    const int lane = threadIdx.x & 31;

    if (g_alldet) {
        // ================= FAST PATH =================
        const int qd      = cb + (threadIdx.x >> 2);   // input column / quad id
        const int quarter = threadIdx.x & 3;           // channel quarter
        const bool active = (qd < W_IN);
        const unsigned pm = 0xFu << (lane & 28);

        if (active) {
            const int xx1 = min(qd + 1, W_IN - 1);
            const ull* pa = (const ull*)(sbuf + (qd  - cb) * CSTRIDE + quarter * QSTRIDE);
            const ull* pb = (const ull*)(sbuf + (xx1 - cb) * CSTRIDE + quarter * QSTRIDE);
            const ull QP = f2x2_pack(0.25f, 0.25f);
            const ull QN = f2x2_pack(-0.25f, -0.25f);

            float s0 = 0.f, s1 = 0.f, s2 = 0.f, s3 = 0.f;
            float bv0 = -FLT_MAX, bv1 = -FLT_MAX, bv2 = -FLT_MAX, bv3 = -FLT_MAX;
            int   bg0 = 0, bg1 = 0, bg2 = 0, bg3 = 0;

            #pragma unroll
            for (int g = 0; g < 8; ++g) {
                ull a01 = pa[2 * g], a23 = pa[2 * g + 1];
                ull b01 = pb[2 * g], b23 = pb[2 * g + 1];
                ull q01 = f2x2_fma(b01, QP, f2x2_mul(a01, QN));
                ull q23 = f2x2_fma(b23, QP, f2x2_mul(a23, QN));
                ull u101 = f2x2_add(a01,  q01), u123 = f2x2_add(a23,  q23);
                ull u201 = f2x2_add(u101, q01), u223 = f2x2_add(u123, q23);
                ull u301 = f2x2_add(u201, q01), u323 = f2x2_add(u223, q23);

                float fa0, fa1, fa2, fa3, fq0, fq1, fq2, fq3;
                f2x2_unpack(a01, fa0, fa1); f2x2_unpack(a23, fa2, fa3);
                f2x2_unpack(q01, fq0, fq1); f2x2_unpack(q23, fq2, fq3);
                float p10, p11, p12, p13, p20, p21, p22, p23, p30, p31, p32, p33;
                f2x2_unpack(u101, p10, p11); f2x2_unpack(u123, p12, p13);
                f2x2_unpack(u201, p20, p21); f2x2_unpack(u223, p22, p23);
                f2x2_unpack(u301, p30, p31); f2x2_unpack(u323, p32, p33);

                // per-pixel group maxes in v-domain (strict >: earliest group)
                float gm0 = fmaxf(fmaxf(fa0, fa1), fmaxf(fa2, fa3));
                float gm1 = fmaxf(fmaxf(p10, p11), fmaxf(p12, p13));
                float gm2 = fmaxf(fmaxf(p20, p21), fmaxf(p22, p23));
                float gm3 = fmaxf(fmaxf(p30, p31), fmaxf(p32, p33));
                if (gm0 > bv0) { bv0 = gm0; bg0 = g; }
                if (gm1 > bv1) { bv1 = gm1; bg1 = g; }
                if (gm2 > bv2) { bv2 = gm2; bg2 = g; }
                if (gm3 > bv3) { bv3 = gm3; bg3 = g; }

                // geometric exp chain: 2 EX2 per channel cover all 4 pixels
                float e0, e1, e2, e3, r0, r1, r2, r3;
                EX2(e0, fa0); EX2(e1, fa1); EX2(e2, fa2); EX2(e3, fa3);
                EX2(r0, fq0); EX2(r1, fq1); EX2(r2, fq2); EX2(r3, fq3);
                s0 += e0; s0 += e1; s0 += e2; s0 += e3;
                s1 = fmaf(e0, r0, s1); s1 = fmaf(e1, r1, s1);
                s1 = fmaf(e2, r2, s1); s1 = fmaf(e3, r3, s1);
                float r20 = r0 * r0, r21 = r1 * r1, r22 = r2 * r2, r23 = r3 * r3;
                s2 = fmaf(e0, r20, s2); s2 = fmaf(e1, r21, s2);
                s2 = fmaf(e2, r22, s2); s2 = fmaf(e3, r23, s2);
                float r30 = r20 * r0, r31 = r21 * r1, r32 = r22 * r2, r33 = r23 * r3;
                s3 = fmaf(e0, r30, s3); s3 = fmaf(e1, r31, s3);
                s3 = fmaf(e2, r32, s3); s3 = fmaf(e3, r33, s3);
            }

            const int ch0 = quarter * 32;
            int bi0 = ch0 + scan_group(pa, pb, QP, QN, bg0, bv0, 0);
            int bi1 = ch0 + scan_group(pa, pb, QP, QN, bg1, bv1, 1);
            int bi2 = ch0 + scan_group(pa, pb, QP, QN, bg2, bv2, 2);
            int bi3 = ch0 + scan_group(pa, pb, QP, QN, bg3, bv3, 3);

            // combine across the 4 channel-quarters (quad shfl)
            #pragma unroll
            for (int off = 1; off <= 2; off <<= 1) {
                s0 += __shfl_xor_sync(pm, s0, off);
                s1 += __shfl_xor_sync(pm, s1, off);
                s2 += __shfl_xor_sync(pm, s2, off);
                s3 += __shfl_xor_sync(pm, s3, off);
                float ob; int oi;
                ob = __shfl_xor_sync(pm, bv0, off); oi = __shfl_xor_sync(pm, bi0, off);
                if (ob > bv0 || (ob == bv0 && oi < bi0)) { bv0 = ob; bi0 = oi; }
                ob = __shfl_xor_sync(pm, bv1, off); oi = __shfl_xor_sync(pm, bi1, off);
                if (ob > bv1 || (ob == bv1 && oi < bi1)) { bv1 = ob; bi1 = oi; }
                ob = __shfl_xor_sync(pm, bv2, off); oi = __shfl_xor_sync(pm, bi2, off);
                if (ob > bv2 || (ob == bv2 && oi < bi2)) { bv2 = ob; bi2 = oi; }
                ob = __shfl_xor_sync(pm, bv3, off); oi = __shfl_xor_sync(pm, bi3, off);
                if (ob > bv3 || (ob == bv3 && oi < bi3)) { bv3 = ob; bi3 = oi; }
            }

            if (quarter == 0) {
                float sv[4]  = { s0, s1, s2, s3 };
                float bvv[4] = { bv0, bv1, bv2, bv3 };
                int   biv[4] = { bi0, bi1, bi2, bi3 };
                #pragma unroll
                for (int p4 = 0; p4 < 4; ++p4) {
                    const int px = 4 * qd + p4;
                    if (px < W_OUT) {
                        // pixel_conf > 0.4  <=>  s < 2.5 * 2^bv; detected_pixel==1
                        float eb; EX2(eb, bvv[p4]);
                        const float cf = (sv[p4] < 2.5f * eb) ? 1.0f : 0.0f;
                        const int bi = biv[p4];
                        const int semI = ssem[bi];
                        const int p = y * W_OUT + px;
                        out[p]            = (float)(smaskid[bi] + 1);
                        out[NPIX + p]     = (float)semI;
                        out[2 * NPIX + p] = (semI < 80)  ? cf : 0.0f;
                        out[3 * NPIX + p] = (semI >= 80) ? cf : 0.0f;
                    }
                }
            }
        }
    } else {
        // ================= GENERAL PATH (rare) =================
        const int px = cb * 4 + threadIdx.x;
        if (px < W_OUT) {
            const int x0 = px >> 2;
            const int x1 = min(x0 + 1, W_IN - 1);
            const float wx   = (float)(px & 3) * 0.25f;
            const float omwx = 1.0f - wx;

            float fm = -FLT_MAX, bv = -FLT_MAX, s = 0.0f;
            int bi = 0;
            #pragma unroll
            for (int quarter = 0; quarter < 4; ++quarter) {
                const ull* pa = (const ull*)(sbuf + (x0 - cb) * CSTRIDE + quarter * QSTRIDE);
                const ull* pb = (const ull*)(sbuf + (x1 - cb) * CSTRIDE + quarter * QSTRIDE);
                const ull* pg = (const ull*)(sbias + quarter * 32);
                #pragma unroll 4
                for (int c2 = 0; c2 < 16; ++c2) {
                    float a0, a1, b0, b1, gg0, gg1;
                    f2x2_unpack(pa[c2], a0, a1);
                    f2x2_unpack(pb[c2], b0, b1);
                    f2x2_unpack(pg[c2], gg0, gg1);
                    {
                        float v = a0 * omwx + b0 * wx;
                        fm = fmaxf(fm, v);
                        float mv = v + gg0;
                        if (mv > bv) { bv = mv; bi = quarter * 32 + 2 * c2; }
                        float e; EX2(e, mv); s += e;
                    }
                    {
                        float v = a1 * omwx + b1 * wx;
                        fm = fmaxf(fm, v);
                        float mv = v + gg1;
                        if (mv > bv) { bv = mv; bi = quarter * 32 + 2 * c2 + 1; }
                        float e; EX2(e, mv); s += e;
                    }
                }
            }
            float eb; EX2(eb, bv);
            const float cf = (s < 2.5f * eb && fm == bv) ? 1.0f : 0.0f;

            float maskid, sem, thing, stuff;
            if (g_hasdet) {
                const int semI = ssem[bi];
                maskid = (float)(smaskid[bi] + 1);
                sem    = (float)semI;
                thing  = (semI < 80)  ? cf : 0.0f;
                stuff  = (semI >= 80) ? cf : 0.0f;
            } else {
                maskid = 1.0f; sem = 0.0f; thing = 0.0f; stuff = 0.0f;
            }
            const int p = y * W_OUT + px;
            out[p]            = maskid;
            out[NPIX + p]     = sem;
            out[2 * NPIX + p] = thing;
            out[3 * NPIX + p] = stuff;
        }
    }
}

// ---------------------------------------------------------------------------
extern "C" void kernel_launch(void* const* d_in, const int* in_sizes, int n_in,
                              void* d_out, int out_size) {
    const float* logits = (const float*)d_in[0];  // (161,161,128)
    const float* probs  = (const float*)d_in[1];  // (128,134)
    if (n_in >= 2 && in_sizes[0] < in_sizes[1]) { // safety: order by size
        const float* t = logits; logits = probs; probs = t;
    }
    float* out = (float*)d_out;

    classify_kernel<<<1, 1024>>>(probs);
    postproc_kernel<<<dim3(3, H_OUT), 256>>>(logits, out);
}

// round 11
// speedup vs baseline: 1.1972x; 1.0129x over previous
#include <cuda_runtime.h>
#include <float.h>

#define H_IN   161
#define W_IN   161
#define C      128
#define H_OUT  641
#define W_OUT  641
#define NPIX   (H_OUT * W_OUT)
#define NEGV   (-1000000000.0f)
#define LOG2E  1.4426950408889634f

#define QPB      54       // quads (input columns) per block
#define NCOLS    55       // columns stored per block (one extra for x1)
#define CSTRIDE  136      // column stride in floats: 136 mod 32 == 8
#define QSTRIDE  34       // quarter stride in floats: 34 mod 32 == 2

typedef unsigned long long ull;

// Per-slot classification results (phase A -> phase B)
__device__ int      g_maskid[128];
__device__ int      g_sem[128];
__device__ unsigned g_detmask[4];
__device__ int      g_hasdet;
__device__ int      g_alldet;

// ---------------------------------------------------------------------------
// Phase A: 1024 threads, 8-way split scan per slot + ballot cumsum.
// ---------------------------------------------------------------------------
__global__ void classify_kernel(const float* __restrict__ probs /*128x134*/) {
    __shared__ unsigned char sdet[128];
    __shared__ unsigned wmask[4];

    const int t    = threadIdx.x;          // 0..1023
    const int lane = t & 31;
    const int s    = t >> 3;               // slot 0..127
    const int part = t & 7;

    const int c0 = part * 17;
    const int c1 = (c0 + 17 < 133) ? (c0 + 17) : 133;
    const float* row = probs + s * 134;
    float best = -FLT_MAX;
    int bi = c0;
    for (int c = c0; c < c1; ++c) {
        float v = row[c];
        if (v > best) { best = v; bi = c; }    // strict >: first occurrence
    }
    const unsigned pm = 0xFFu << (lane & 24);
    #pragma unroll
    for (int off = 1; off <= 4; off <<= 1) {
        float ob  = __shfl_xor_sync(pm, best, off);
        int   obi = __shfl_xor_sync(pm, bi,   off);
        if (ob > best || (ob == best && obi < bi)) { best = ob; bi = obi; }
    }
    if (part == 0) {
        g_sem[s] = bi;
        sdet[s]  = (best >= 0.7f) ? 1 : 0;
    }
    __syncthreads();

    unsigned b = 0;
    if (t < 128) {
        b = __ballot_sync(0xffffffffu, sdet[t] != 0);
        if (lane == 0) wmask[t >> 5] = b;
    }
    __syncthreads();

    if (t < 128) {
        int cnt = __popc(b & (0xffffffffu >> (31 - lane)));
        for (int k = 0; k < (t >> 5); ++k) cnt += __popc(wmask[k]);
        g_maskid[t] = cnt - 1;
        if (t == 0) {
            int tot = __popc(wmask[0]) + __popc(wmask[1]) +
                      __popc(wmask[2]) + __popc(wmask[3]);
            g_detmask[0] = wmask[0]; g_detmask[1] = wmask[1];
            g_detmask[2] = wmask[2]; g_detmask[3] = wmask[3];
            g_hasdet = (tot > 0)   ? 1 : 0;
            g_alldet = (tot == 128)? 1 : 0;
        }
    }
}

// ---------------------------------------------------------------------------
// Packed f32x2 helpers
// ---------------------------------------------------------------------------
__device__ __forceinline__ ull f2x2_mul(ull a, ull b) {
    ull r; asm("mul.rn.f32x2 %0, %1, %2;" : "=l"(r) : "l"(a), "l"(b)); return r;
}
__device__ __forceinline__ ull f2x2_fma(ull a, ull b, ull c) {
    ull r; asm("fma.rn.f32x2 %0, %1, %2, %3;" : "=l"(r) : "l"(a), "l"(b), "l"(c)); return r;
}
__device__ __forceinline__ ull f2x2_pack(float lo, float hi) {
    ull r; asm("mov.b64 %0, {%1, %2};" : "=l"(r) : "f"(lo), "f"(hi)); return r;
}
__device__ __forceinline__ void f2x2_unpack(ull v, float& lo, float& hi) {
    asm("mov.b64 {%0, %1}, %2;" : "=f"(lo), "=f"(hi) : "l"(v));
}
#define EX2(dst, src) asm("ex2.approx.f32 %0, %1;" : "=f"(dst) : "f"(src))

// Epilogue: within-group channel of the per-pixel max in EXP domain.
// Bit-identical recomputation of the main-loop t chain (same mul order);
// first occurrence on ties (scan high->low, overwrite).
__device__ __forceinline__ int scan_group_exp(const ull* pa, const ull* pb,
                                              ull QP, ull QN,
                                              int bg, float m, int p) {
    ull a01 = pa[2 * bg], a23 = pa[2 * bg + 1];
    ull b01 = pb[2 * bg], b23 = pb[2 * bg + 1];
    ull q01 = f2x2_fma(b01, QP, f2x2_mul(a01, QN));
    ull q23 = f2x2_fma(b23, QP, f2x2_mul(a23, QN));
    float fa0, fa1, fa2, fa3, fq0, fq1, fq2, fq3;
    f2x2_unpack(a01, fa0, fa1); f2x2_unpack(a23, fa2, fa3);
    f2x2_unpack(q01, fq0, fq1); f2x2_unpack(q23, fq2, fq3);
    float t0, t1, t2, t3, r0, r1, r2, r3;
    EX2(t0, fa0); EX2(t1, fa1); EX2(t2, fa2); EX2(t3, fa3);
    EX2(r0, fq0); EX2(r1, fq1); EX2(r2, fq2); EX2(r3, fq3);
    for (int k = 0; k < p; ++k) { t0 *= r0; t1 *= r1; t2 *= r2; t3 *= r3; }
    int r = 3;
    if (t2 == m) r = 2;
    if (t1 == m) r = 1;
    if (t0 == m) r = 0;
    return 4 * bg + r;
}

// ---------------------------------------------------------------------------
// Phase B: grid (3, 641). Block = one 54-column segment of one row, 256 thr.
// SMEM: per-column 4 quarter-groups of 32 ch, pads keep LDS.64 conflict-free.
// Fast path: thread = (quad, channel-quarter). Per channel: EX2(a) + EX2(q);
// the geometric terms t = e*r^p feed BOTH the softmax sums and (exp-domain)
// the per-pixel maxes -- no v-domain chains, no final EX2.
// ---------------------------------------------------------------------------
__global__ void __launch_bounds__(256, 5)
postproc_kernel(const float* __restrict__ in, float* __restrict__ out) {
    __shared__ float sbuf[NCOLS * CSTRIDE];   // 29920 B
    __shared__ float sbias[128];
    __shared__ int   ssem[128];
    __shared__ int   smaskid[128];

    const int y  = blockIdx.y;
    const int y0 = y >> 2;
    const int y1 = min(y0 + 1, H_IN - 1);
    const float wy = (float)(y & 3) * 0.25f;
    const float w1 = wy * LOG2E;
    const float w0 = (1.0f - wy) * LOG2E;

    const int cb = blockIdx.x * QPB;           // 0 / 54 / 108
    const int nc = min(NCOLS, W_IN - cb);      // 55 / 55 / 53

    // ---- fill: y-lerp (log2e-prescaled) into padded SMEM ----
    {
        const float4* r0 = (const float4*)(in + ((size_t)y0 * W_IN + cb) * C);
        const float4* r1 = (const float4*)(in + ((size_t)y1 * W_IN + cb) * C);
        const int nv = nc * 32;   // float4 count
        if ((y & 3) == 0) {
            #pragma unroll 4
            for (int i = threadIdx.x; i < nv; i += 256) {
                float4 a = r0[i];
                float* dst = sbuf + (i >> 5) * CSTRIDE
                                  + ((i & 31) >> 3) * QSTRIDE + (i & 7) * 4;
                *(float2*)(dst)     = make_float2(a.x * w0, a.y * w0);
                *(float2*)(dst + 2) = make_float2(a.z * w0, a.w * w0);
            }
        } else {
            #pragma unroll 4
            for (int i = threadIdx.x; i < nv; i += 256) {
                float4 a = r0[i], b = r1[i];
                float* dst = sbuf + (i >> 5) * CSTRIDE
                                  + ((i & 31) >> 3) * QSTRIDE + (i & 7) * 4;
                *(float2*)(dst)     = make_float2(a.x * w0 + b.x * w1, a.y * w0 + b.y * w1);
                *(float2*)(dst + 2) = make_float2(a.z * w0 + b.z * w1, a.w * w0 + b.w * w1);
            }
        }
        if (threadIdx.x < 128) {
            unsigned m = g_detmask[threadIdx.x >> 5];
            sbias[threadIdx.x] = ((m >> (threadIdx.x & 31)) & 1u) ? 0.0f : NEGV;
            ssem[threadIdx.x]    = g_sem[threadIdx.x];
            smaskid[threadIdx.x] = g_maskid[threadIdx.x];
        }
    }
    __syncthreads();

    const int lane = threadIdx.x & 31;

    if (g_alldet) {
        // ================= FAST PATH =================
        const int qrel    = threadIdx.x >> 2;          // quad within block
        const int qd      = cb + qrel;                 // input column
        const int quarter = threadIdx.x & 3;           // channel quarter
        const bool active = (qrel < QPB) && (qd < W_IN);
        const unsigned pm = 0xFu << (lane & 28);

        if (active) {
            const int xx1 = min(qd + 1, W_IN - 1);
            const ull* pa = (const ull*)(sbuf + (qd  - cb) * CSTRIDE + quarter * QSTRIDE);
            const ull* pb = (const ull*)(sbuf + (xx1 - cb) * CSTRIDE + quarter * QSTRIDE);
            const ull QP = f2x2_pack(0.25f, 0.25f);
            const ull QN = f2x2_pack(-0.25f, -0.25f);

            float s0 = 0.f, s1 = 0.f, s2 = 0.f, s3 = 0.f;
            float m0 = 0.f, m1 = 0.f, m2 = 0.f, m3 = 0.f;   // exp-domain maxes (t >= 0)
            int   bg0 = 0, bg1 = 0, bg2 = 0, bg3 = 0;

            #pragma unroll
            for (int g = 0; g < 8; ++g) {
                ull a01 = pa[2 * g], a23 = pa[2 * g + 1];
                ull b01 = pb[2 * g], b23 = pb[2 * g + 1];
                ull q01 = f2x2_fma(b01, QP, f2x2_mul(a01, QN));
                ull q23 = f2x2_fma(b23, QP, f2x2_mul(a23, QN));

                float fa0, fa1, fa2, fa3, fq0, fq1, fq2, fq3;
                f2x2_unpack(a01, fa0, fa1); f2x2_unpack(a23, fa2, fa3);
                f2x2_unpack(q01, fq0, fq1); f2x2_unpack(q23, fq2, fq3);

                float e0, e1, e2, e3, r0, r1, r2, r3;
                EX2(e0, fa0); EX2(e1, fa1); EX2(e2, fa2); EX2(e3, fa3);
                EX2(r0, fq0); EX2(r1, fq1); EX2(r2, fq2); EX2(r3, fq3);

                // pixel 0: terms are e directly
                float gm0 = fmaxf(fmaxf(e0, e1), fmaxf(e2, e3));
                s0 += e0; s0 += e1; s0 += e2; s0 += e3;
                // pixel 1
                float t10 = e0 * r0, t11 = e1 * r1, t12 = e2 * r2, t13 = e3 * r3;
                float gm1 = fmaxf(fmaxf(t10, t11), fmaxf(t12, t13));
                s1 += t10; s1 += t11; s1 += t12; s1 += t13;
                // pixel 2
                float t20 = t10 * r0, t21 = t11 * r1, t22 = t12 * r2, t23 = t13 * r3;
                float gm2 = fmaxf(fmaxf(t20, t21), fmaxf(t22, t23));
                s2 += t20; s2 += t21; s2 += t22; s2 += t23;
                // pixel 3
                float t30 = t20 * r0, t31 = t21 * r1, t32 = t22 * r2, t33 = t23 * r3;
                float gm3 = fmaxf(fmaxf(t30, t31), fmaxf(t32, t33));
                s3 += t30; s3 += t31; s3 += t32; s3 += t33;

                if (gm0 > m0) { m0 = gm0; bg0 = g; }   // strict >: earliest group
                if (gm1 > m1) { m1 = gm1; bg1 = g; }
                if (gm2 > m2) { m2 = gm2; bg2 = g; }
                if (gm3 > m3) { m3 = gm3; bg3 = g; }
            }

            const int ch0 = quarter * 32;
            int bi0 = ch0 + scan_group_exp(pa, pb, QP, QN, bg0, m0, 0);
            int bi1 = ch0 + scan_group_exp(pa, pb, QP, QN, bg1, m1, 1);
            int bi2 = ch0 + scan_group_exp(pa, pb, QP, QN, bg2, m2, 2);
            int bi3 = ch0 + scan_group_exp(pa, pb, QP, QN, bg3, m3, 3);

            // combine across the 4 channel-quarters (quad shfl)
            #pragma unroll
            for (int off = 1; off <= 2; off <<= 1) {
                s0 += __shfl_xor_sync(pm, s0, off);
                s1 += __shfl_xor_sync(pm, s1, off);
                s2 += __shfl_xor_sync(pm, s2, off);
                s3 += __shfl_xor_sync(pm, s3, off);
                float om; int oi;
                om = __shfl_xor_sync(pm, m0, off); oi = __shfl_xor_sync(pm, bi0, off);
                if (om > m0 || (om == m0 && oi < bi0)) { m0 = om; bi0 = oi; }
                om = __shfl_xor_sync(pm, m1, off); oi = __shfl_xor_sync(pm, bi1, off);
                if (om > m1 || (om == m1 && oi < bi1)) { m1 = om; bi1 = oi; }
                om = __shfl_xor_sync(pm, m2, off); oi = __shfl_xor_sync(pm, bi2, off);
                if (om > m2 || (om == m2 && oi < bi2)) { m2 = om; bi2 = oi; }
                om = __shfl_xor_sync(pm, m3, off); oi = __shfl_xor_sync(pm, bi3, off);
                if (om > m3 || (om == m3 && oi < bi3)) { m3 = om; bi3 = oi; }
            }

            if (quarter == 0) {
                float sv[4] = { s0, s1, s2, s3 };
                float mv[4] = { m0, m1, m2, m3 };
                int   biv[4] = { bi0, bi1, bi2, bi3 };
                #pragma unroll
                for (int p4 = 0; p4 < 4; ++p4) {
                    const int px = 4 * qd + p4;
                    if (px < W_OUT) {
                        // pixel_conf > 0.4  <=>  s < 2.5 * m (m = 2^det_max)
                        const float cf = (sv[p4] < 2.5f * mv[p4]) ? 1.0f : 0.0f;
                        const int bi = biv[p4];
                        const int semI = ssem[bi];
                        const int p = y * W_OUT + px;
                        out[p]            = (float)(smaskid[bi] + 1);
                        out[NPIX + p]     = (float)semI;
                        out[2 * NPIX + p] = (semI < 80)  ? cf : 0.0f;
                        out[3 * NPIX + p] = (semI >= 80) ? cf : 0.0f;
                    }
                }
            }
        }
    } else {
        // ================= GENERAL PATH (rare) =================
        const int px = 4 * cb + threadIdx.x;
        if (threadIdx.x < 4 * QPB && px < W_OUT) {
            const int x0 = px >> 2;
            const int x1 = min(x0 + 1, W_IN - 1);
            const float wx   = (float)(px & 3) * 0.25f;
            const float omwx = 1.0f - wx;

            float fm = -FLT_MAX, bv = -FLT_MAX, s = 0.0f;
            int bi = 0;
            #pragma unroll
            for (int quarter = 0; quarter < 4; ++quarter) {
                const ull* pa = (const ull*)(sbuf + (x0 - cb) * CSTRIDE + quarter * QSTRIDE);
                const ull* pb = (const ull*)(sbuf + (x1 - cb) * CSTRIDE + quarter * QSTRIDE);
                const ull* pg = (const ull*)(sbias + quarter * 32);
                #pragma unroll 4
                for (int c2 = 0; c2 < 16; ++c2) {
                    float a0, a1, b0, b1, gg0, gg1;
                    f2x2_unpack(pa[c2], a0, a1);
                    f2x2_unpack(pb[c2], b0, b1);
                    f2x2_unpack(pg[c2], gg0, gg1);
                    {
                        float v = a0 * omwx + b0 * wx;
                        fm = fmaxf(fm, v);
                        float mv = v + gg0;
                        if (mv > bv) { bv = mv; bi = quarter * 32 + 2 * c2; }
                        float e; EX2(e, mv); s += e;
                    }
                    {
                        float v = a1 * omwx + b1 * wx;
                        fm = fmaxf(fm, v);
                        float mv = v + gg1;
                        if (mv > bv) { bv = mv; bi = quarter * 32 + 2 * c2 + 1; }
                        float e; EX2(e, mv); s += e;
                    }
                }
            }
            float eb; EX2(eb, bv);
            const float cf = (s < 2.5f * eb && fm == bv) ? 1.0f : 0.0f;

            float maskid, sem, thing, stuff;
            if (g_hasdet) {
                const int semI = ssem[bi];
                maskid = (float)(smaskid[bi] + 1);
                sem    = (float)semI;
                thing  = (semI < 80)  ? cf : 0.0f;
                stuff  = (semI >= 80) ? cf : 0.0f;
            } else {
                maskid = 1.0f; sem = 0.0f; thing = 0.0f; stuff = 0.0f;
            }
            const int p = y * W_OUT + px;
            out[p]            = maskid;
            out[NPIX + p]     = sem;
            out[2 * NPIX + p] = thing;
            out[3 * NPIX + p] = stuff;
        }
    }
}

// ---------------------------------------------------------------------------
extern "C" void kernel_launch(void* const* d_in, const int* in_sizes, int n_in,
                              void* d_out, int out_size) {
    const float* logits = (const float*)d_in[0];  // (161,161,128)
    const float* probs  = (const float*)d_in[1];  // (128,134)
    if (n_in >= 2 && in_sizes[0] < in_sizes[1]) { // safety: order by size
        const float* t = logits; logits = probs; probs = t;
    }
    float* out = (float*)d_out;

    classify_kernel<<<1, 1024>>>(probs);
    postproc_kernel<<<dim3(3, H_OUT), 256>>>(logits, out);
}